// round 8
// baseline (speedup 1.0000x reference)
#include <cuda_runtime.h>
#include <cstdint>

#define T_MAX   32768
#define NLM     543
#define FROW    (NLM*3)        // 1629 floats per frame
#define NL      512            // NORMALIZED_LENGTH
#define NCOL    122            // 61 landmarks x 2
#define SCW     128            // padded scratch row width (floats); cols 122..127 stay 0
#define NB1     1024           // k1 blocks (32 frames each)
#define FPW     4              // frames per warp in k1

// ------------------------- device scratch (static, no allocs) ---------------
__device__ float g_scratch[(size_t)T_MAX * SCW]; // [t][0..41]=hand, [42..121]=lips(raw, may be NaN)
__device__ __align__(16) unsigned g_keepw[1024]; // word b = frames b*32..b*32+31
__device__ int   g_idx[T_MAX];                   // compact s -> original frame t
__device__ int   g_b[NL + 1];
__device__ float g_lipsum[80];
__device__ int   g_lipcnt[80];
__device__ float g_lipmean[96];                  // padded: [80..95] stay 0 (pad-col gathers)
__device__ int   g_rowoff[NL];

__device__ __forceinline__ float nan0(float v) { return (v == v) ? v : 0.0f; }

// ------------------------- K1: per-frame hand/keep/lips ---------------------
// 1024 blocks x 256 threads; 8 warps/block, 4 consecutive frames per warp.
// Two-phase: batch ALL loads first (max MLP), then ballots/stores/accumulate.
__global__ void k1(const float* __restrict__ fr, const int* __restrict__ lips) {
    __shared__ float    ssum[80];
    __shared__ int      scnt[80];
    __shared__ unsigned kbsh[8];
    int tid  = threadIdx.x;
    int lane = tid & 31;
    int warp = tid >> 5;
    if (tid < 80) { ssum[tid] = 0.0f; scnt[tid] = 0; }
    __syncthreads();

    int base = blockIdx.x * 32 + warp * FPW;

    int li0 = lips[lane];            // lips 0..31 (lane-indexed)
    int li1 = 0;
    if (lane < 8) li1 = lips[lane + 32];

    // ---------------- phase A: issue every load ----------------
    float lx[FPW], ly[FPW], rx[FPW], ry[FPW];
    float x0[FPW], y0[FPW], x1[FPW], y1[FPW];
    #pragma unroll
    for (int i = 0; i < FPW; i++) {
        const float* f = fr + (size_t)(base + i) * FROW;
        if (lane < 21) {
            lx[i] = f[1404 + 3 * lane];   // (468+l)*3
            ly[i] = f[1405 + 3 * lane];
            rx[i] = f[1566 + 3 * lane];   // (522+l)*3
            ry[i] = f[1567 + 3 * lane];
        }
        x0[i] = f[3 * li0];
        y0[i] = f[3 * li0 + 1];
        if (lane < 8) {
            x1[i] = f[3 * li1];
            y1[i] = f[3 * li1 + 1];
        }
    }

    // ---------------- phase B: compute / store / accumulate ----------------
    float ls0 = 0.f, ls1 = 0.f, ls2 = 0.f, ls3 = 0.f;
    int   lc0 = 0,   lc1 = 0,   lc2 = 0,   lc3 = 0;
    unsigned kbits = 0;

    #pragma unroll
    for (int i = 0; i < FPW; i++) {
        float2* sc = (float2*)(g_scratch + (size_t)(base + i) * SCW);
        float h0 = 0.f, h1 = 0.f;
        if (lane < 21) {
            h0 = nan0(lx[i]) + nan0(1.0f - rx[i]);
            h1 = nan0(1.0f - ly[i]) + nan0(1.0f - ry[i]);
            sc[lane] = make_float2(h0, h1);
        }
        // all hand components >= 0, so sum != 0  <=>  any component != 0
        unsigned anyb = __ballot_sync(0xffffffffu, (h0 + h1) != 0.0f);
        int kp = anyb ? 1 : 0;
        kbits |= (unsigned)kp << i;

        sc[21 + lane] = make_float2(x0[i], y0[i]);
        if (lane < 8) sc[53 + lane] = make_float2(x1[i], y1[i]);

        if (kp) {
            if (x0[i] == x0[i]) { ls0 += x0[i]; lc0++; }
            if (y0[i] == y0[i]) { ls1 += y0[i]; lc1++; }
            if (lane < 8) {
                if (x1[i] == x1[i]) { ls2 += x1[i]; lc2++; }
                if (y1[i] == y1[i]) { ls3 += y1[i]; lc3++; }
            }
        }
    }

    if (lane == 0) kbsh[warp] = kbits;

    atomicAdd(&ssum[2 * lane],     ls0);
    atomicAdd(&ssum[2 * lane + 1], ls1);
    atomicAdd(&scnt[2 * lane],     lc0);
    atomicAdd(&scnt[2 * lane + 1], lc1);
    if (lane < 8) {
        int c = 64 + 2 * lane;
        atomicAdd(&ssum[c],     ls2);
        atomicAdd(&ssum[c + 1], ls3);
        atomicAdd(&scnt[c],     lc2);
        atomicAdd(&scnt[c + 1], lc3);
    }
    __syncthreads();
    if (tid == 0) {
        unsigned w = 0;
        #pragma unroll
        for (int q = 0; q < 8; q++) w |= kbsh[q] << (4 * q);
        g_keepw[blockIdx.x] = w;
    }
    if (tid < 80) {
        atomicAdd(&g_lipsum[tid], ssum[tid]);
        atomicAdd(&g_lipcnt[tid], scnt[tid]);
    }
}

// -------- K2: scan, boundaries, row offsets, lip means, compaction (1 blk) --
__global__ void k2() {
    __shared__ int sc[256];
    __shared__ int sr[NL];
    int t = threadIdx.x;

    // thread t owns frames t*128 .. t*128+127 via 4 keep words (uint4)
    uint4 kb = ((const uint4*)g_keepw)[t];
    int cnt = __popc(kb.x) + __popc(kb.y) + __popc(kb.z) + __popc(kb.w);
    sc[t] = cnt;
    __syncthreads();
    for (int o = 1; o < 256; o <<= 1) {
        int a = (t >= o) ? sc[t - o] : 0;
        __syncthreads();
        sc[t] += a;
        __syncthreads();
    }
    int off = sc[t] - cnt;   // exclusive prefix for this chunk
    int S = sc[255];

    // order-preserving compaction: thread t writes its own kept frames
    {
        unsigned ws[4] = {kb.x, kb.y, kb.z, kb.w};
        int tb = t * 128;
        #pragma unroll
        for (int q = 0; q < 4; q++) {
            unsigned m = ws[q];
            int fb = tb + q * 32;
            while (m) {
                int p = __ffs(m) - 1;
                m &= m - 1;
                g_idx[off++] = fb + p;
            }
        }
    }

    // b = np.linspace(0, S-1, 513).astype(int32)
    double step = (double)(S - 1) / 512.0;
    for (int k = t; k < NL + 1; k += 256)
        g_b[k] = (k == NL) ? (S - 1) : (int)((double)k * step);
    __syncthreads();

    // row kept  <=>  segment count > 0 (all values nonnegative, kept frames
    // have strictly positive hand sum => row sum > 0). Exclusive scan of flags.
    int f0 = (g_b[t + 1]   > g_b[t])       ? 1 : 0;
    int f1 = (g_b[t + 257] > g_b[t + 256]) ? 1 : 0;
    sr[t] = f0; sr[t + 256] = f1;
    __syncthreads();
    for (int o = 1; o < NL; o <<= 1) {
        int v0 = sr[t]       + ((t       >= o) ? sr[t - o]       : 0);
        int v1 = sr[t + 256] + ((t + 256 >= o) ? sr[t + 256 - o] : 0);
        __syncthreads();
        sr[t] = v0; sr[t + 256] = v1;
        __syncthreads();
    }
    g_rowoff[t]       = sr[t]       - f0;
    g_rowoff[t + 256] = sr[t + 256] - f1;

    if (t < 80) {
        int   c = g_lipcnt[t];
        float s = g_lipsum[t];
        g_lipmean[t] = (c == 0) ? 0.0f : s / (float)max(c, 1);
    }
}

// ---------- K3: segment means -> compacted output rows ----------------------
// 512 blocks x 256 threads = 8 warps. Warp w sums frames i = w, w+8, ...
// Each lane covers 4 columns via one float4 load per frame (coalesced 512B/row).
__global__ void k3(float* __restrict__ out) {
    int k    = blockIdx.x;
    int tid  = threadIdx.x;
    int w    = tid >> 5;
    int lane = tid & 31;

    // reset accumulators for next graph replay (k2 already consumed them)
    if (k == 0 && tid < 80) { g_lipsum[tid] = 0.0f; g_lipcnt[tid] = 0; }

    __shared__ int   sidx[64];
    __shared__ float part[8][128];
    int s0 = g_b[k];
    int cnt = g_b[k + 1] - s0;          // <= 64 for S <= 32768
    if (cnt <= 0) return;
    if (tid < cnt) sidx[tid] = g_idx[s0 + tid];
    __syncthreads();

    int col = lane * 4;
    // lm per column: hand cols (<42) never NaN -> 0; pad cols 122..127 read
    // g_lipmean[80..85] which are static zeros (never matter: pad values are 0).
    float4 lm;
    lm.x = (col + 0 >= 42) ? g_lipmean[col + 0 - 42] : 0.0f;
    lm.y = (col + 1 >= 42) ? g_lipmean[col + 1 - 42] : 0.0f;
    lm.z = (col + 2 >= 42) ? g_lipmean[col + 2 - 42] : 0.0f;
    lm.w = (col + 3 >= 42) ? g_lipmean[col + 3 - 42] : 0.0f;

    float4 a0 = make_float4(0.f, 0.f, 0.f, 0.f);
    float4 a1 = make_float4(0.f, 0.f, 0.f, 0.f);
    int i = w;
    for (; i + 8 < cnt; i += 16) {
        float4 v0 = *(const float4*)(g_scratch + (size_t)sidx[i]     * SCW + col);
        float4 v1 = *(const float4*)(g_scratch + (size_t)sidx[i + 8] * SCW + col);
        a0.x += (v0.x == v0.x) ? v0.x : lm.x;
        a0.y += (v0.y == v0.y) ? v0.y : lm.y;
        a0.z += (v0.z == v0.z) ? v0.z : lm.z;
        a0.w += (v0.w == v0.w) ? v0.w : lm.w;
        a1.x += (v1.x == v1.x) ? v1.x : lm.x;
        a1.y += (v1.y == v1.y) ? v1.y : lm.y;
        a1.z += (v1.z == v1.z) ? v1.z : lm.z;
        a1.w += (v1.w == v1.w) ? v1.w : lm.w;
    }
    for (; i < cnt; i += 8) {
        float4 v = *(const float4*)(g_scratch + (size_t)sidx[i] * SCW + col);
        a0.x += (v.x == v.x) ? v.x : lm.x;
        a0.y += (v.y == v.y) ? v.y : lm.y;
        a0.z += (v.z == v.z) ? v.z : lm.z;
        a0.w += (v.w == v.w) ? v.w : lm.w;
    }
    a0.x += a1.x; a0.y += a1.y; a0.z += a1.z; a0.w += a1.w;
    *(float4*)&part[w][col] = a0;
    __syncthreads();

    if (tid < NCOL) {
        float s = 0.f;
        #pragma unroll
        for (int q = 0; q < 8; q++) s += part[q][tid];
        out[(size_t)g_rowoff[k] * NCOL + tid] = s / (float)cnt;
    }
}

// ------------------------- launch -------------------------------------------
extern "C" void kernel_launch(void* const* d_in, const int* in_sizes, int n_in,
                              void* d_out, int out_size) {
    const float* frames = (const float*)d_in[0];
    const int*   lips   = (const int*)d_in[1];

    k1<<<NB1, 256>>>(frames, lips);
    k2<<<1, 256>>>();
    k3<<<NL, 256>>>((float*)d_out);
}

// round 12
// speedup vs baseline: 1.3770x; 1.3770x over previous
#include <cuda_runtime.h>
#include <cstdint>

#define T_MAX   32768
#define NLM     543
#define FROW    (NLM*3)        // 1629 floats per frame
#define NL      512            // NORMALIZED_LENGTH
#define NCOL    122            // 61 landmarks x 2
#define SCW     128            // padded scratch row width (floats); cols 122..127 stay 0
#define NB1     1024           // k1 blocks (32 frames each)
#define FPW     4              // frames per warp in k1

// ------------------------- device scratch (static, no allocs) ---------------
__device__ float g_scratch[(size_t)T_MAX * SCW]; // [t][0..41]=hand, [42..121]=lips(raw, may be NaN)
__device__ __align__(16) unsigned g_keepw[1024]; // word b = frames b*32..b*32+31
__device__ int   g_chunkoff[256];                // exclusive kept-count per 128-frame chunk
__device__ int   g_idx[T_MAX];                   // compact s -> original frame t
__device__ int   g_b[NL + 1];
__device__ float g_lipsum[80];
__device__ int   g_lipcnt[80];
__device__ float g_lipmean[96];                  // padded: [80..95] stay 0 (pad-col gathers)
__device__ int   g_rowoff[NL];

__device__ __forceinline__ float nan0(float v) { return (v == v) ? v : 0.0f; }

// ------------------------- K1: per-frame hand/keep/lips ---------------------
// 1024 blocks x 256 threads; 8 warps/block, 4 consecutive frames per warp.
// Two-phase: batch ALL loads first (max MLP), then ballots/stores/accumulate.
__global__ void k1(const float* __restrict__ fr, const int* __restrict__ lips) {
    __shared__ float    ssum[80];
    __shared__ int      scnt[80];
    __shared__ unsigned kbsh[8];
    int tid  = threadIdx.x;
    int lane = tid & 31;
    int warp = tid >> 5;
    if (tid < 80) { ssum[tid] = 0.0f; scnt[tid] = 0; }
    __syncthreads();

    int base = blockIdx.x * 32 + warp * FPW;

    int li0 = lips[lane];            // lips 0..31 (lane-indexed)
    int li1 = 0;
    if (lane < 8) li1 = lips[lane + 32];

    // ---------------- phase A: issue every load ----------------
    float lx[FPW], ly[FPW], rx[FPW], ry[FPW];
    float x0[FPW], y0[FPW], x1[FPW], y1[FPW];
    #pragma unroll
    for (int i = 0; i < FPW; i++) {
        const float* f = fr + (size_t)(base + i) * FROW;
        if (lane < 21) {
            lx[i] = f[1404 + 3 * lane];   // (468+l)*3
            ly[i] = f[1405 + 3 * lane];
            rx[i] = f[1566 + 3 * lane];   // (522+l)*3
            ry[i] = f[1567 + 3 * lane];
        }
        x0[i] = f[3 * li0];
        y0[i] = f[3 * li0 + 1];
        if (lane < 8) {
            x1[i] = f[3 * li1];
            y1[i] = f[3 * li1 + 1];
        }
    }

    // ---------------- phase B: compute / store / accumulate ----------------
    float ls0 = 0.f, ls1 = 0.f, ls2 = 0.f, ls3 = 0.f;
    int   lc0 = 0,   lc1 = 0,   lc2 = 0,   lc3 = 0;
    unsigned kbits = 0;

    #pragma unroll
    for (int i = 0; i < FPW; i++) {
        float2* sc = (float2*)(g_scratch + (size_t)(base + i) * SCW);
        float h0 = 0.f, h1 = 0.f;
        if (lane < 21) {
            h0 = nan0(lx[i]) + nan0(1.0f - rx[i]);
            h1 = nan0(1.0f - ly[i]) + nan0(1.0f - ry[i]);
            sc[lane] = make_float2(h0, h1);
        }
        // all hand components >= 0, so sum != 0  <=>  any component != 0
        unsigned anyb = __ballot_sync(0xffffffffu, (h0 + h1) != 0.0f);
        int kp = anyb ? 1 : 0;
        kbits |= (unsigned)kp << i;

        sc[21 + lane] = make_float2(x0[i], y0[i]);
        if (lane < 8) sc[53 + lane] = make_float2(x1[i], y1[i]);

        if (kp) {
            if (x0[i] == x0[i]) { ls0 += x0[i]; lc0++; }
            if (y0[i] == y0[i]) { ls1 += y0[i]; lc1++; }
            if (lane < 8) {
                if (x1[i] == x1[i]) { ls2 += x1[i]; lc2++; }
                if (y1[i] == y1[i]) { ls3 += y1[i]; lc3++; }
            }
        }
    }

    if (lane == 0) kbsh[warp] = kbits;

    atomicAdd(&ssum[2 * lane],     ls0);
    atomicAdd(&ssum[2 * lane + 1], ls1);
    atomicAdd(&scnt[2 * lane],     lc0);
    atomicAdd(&scnt[2 * lane + 1], lc1);
    if (lane < 8) {
        int c = 64 + 2 * lane;
        atomicAdd(&ssum[c],     ls2);
        atomicAdd(&ssum[c + 1], ls3);
        atomicAdd(&scnt[c],     lc2);
        atomicAdd(&scnt[c + 1], lc3);
    }
    __syncthreads();
    if (tid == 0) {
        unsigned w = 0;
        #pragma unroll
        for (int q = 0; q < 8; q++) w |= kbsh[q] << (4 * q);
        g_keepw[blockIdx.x] = w;
    }
    if (tid < 80) {
        atomicAdd(&g_lipsum[tid], ssum[tid]);
        atomicAdd(&g_lipcnt[tid], scnt[tid]);
    }
}

// -------- K2: count scan, boundaries, row offsets, lip means (1 block) ------
__global__ void k2() {
    __shared__ int sc[256];
    __shared__ int sr[NL];
    int t = threadIdx.x;

    // thread t owns frames t*128 .. t*128+127 via 4 keep words (uint4)
    uint4 kb = ((const uint4*)g_keepw)[t];
    int cnt = __popc(kb.x) + __popc(kb.y) + __popc(kb.z) + __popc(kb.w);
    sc[t] = cnt;
    __syncthreads();
    for (int o = 1; o < 256; o <<= 1) {
        int a = (t >= o) ? sc[t - o] : 0;
        __syncthreads();
        sc[t] += a;
        __syncthreads();
    }
    g_chunkoff[t] = sc[t] - cnt;   // exclusive prefix
    int S = sc[255];

    // b = np.linspace(0, S-1, 513).astype(int32)
    double step = (double)(S - 1) / 512.0;
    for (int k = t; k < NL + 1; k += 256)
        g_b[k] = (k == NL) ? (S - 1) : (int)((double)k * step);
    __syncthreads();

    // row kept  <=>  segment count > 0 (all values nonnegative, kept frames
    // have strictly positive hand sum => row sum > 0). Exclusive scan of flags.
    int f0 = (g_b[t + 1]   > g_b[t])       ? 1 : 0;
    int f1 = (g_b[t + 257] > g_b[t + 256]) ? 1 : 0;
    sr[t] = f0; sr[t + 256] = f1;
    __syncthreads();
    for (int o = 1; o < NL; o <<= 1) {
        int v0 = sr[t]       + ((t       >= o) ? sr[t - o]       : 0);
        int v1 = sr[t + 256] + ((t + 256 >= o) ? sr[t + 256 - o] : 0);
        __syncthreads();
        sr[t] = v0; sr[t + 256] = v1;
        __syncthreads();
    }
    g_rowoff[t]       = sr[t]       - f0;
    g_rowoff[t + 256] = sr[t + 256] - f1;

    if (t < 80) {
        int   c = g_lipcnt[t];
        float s = g_lipsum[t];
        g_lipmean[t] = (c == 0) ? 0.0f : s / (float)max(c, 1);
    }
}

// ---------- K2b: order-preserving compaction from bitmask (parallel) --------
__global__ void k2b() {   // grid = 256, 128 threads (one 128-frame chunk each)
    __shared__ unsigned w[4];
    int j = threadIdx.x;
    int b = blockIdx.x;
    if (j < 4) w[j] = g_keepw[b * 4 + j];
    __syncthreads();
    unsigned w0 = w[0], w1 = w[1], w2 = w[2], w3 = w[3];
    int word = j >> 5, bit = j & 31;
    unsigned mw = (word == 0) ? w0 : (word == 1) ? w1 : (word == 2) ? w2 : w3;
    int kp  = (mw >> bit) & 1;
    int pre = __popc(mw & ((1u << bit) - 1u));
    if (word > 0) pre += __popc(w0);
    if (word > 1) pre += __popc(w1);
    if (word > 2) pre += __popc(w2);
    if (kp) g_idx[g_chunkoff[b] + pre] = b * 128 + j;
}

// ---------- K3: segment means -> compacted output rows ----------------------
// 512 blocks x 256 threads = 8 warps. Warp w sums frames i = w, w+8, ...
// Each lane covers 4 columns via one float4 load per frame (coalesced 512B/row).
__global__ void k3(float* __restrict__ out) {
    int k    = blockIdx.x;
    int tid  = threadIdx.x;
    int w    = tid >> 5;
    int lane = tid & 31;

    // reset accumulators for next graph replay (k2 already consumed them)
    if (k == 0 && tid < 80) { g_lipsum[tid] = 0.0f; g_lipcnt[tid] = 0; }

    __shared__ int   sidx[64];
    __shared__ float part[8][128];
    int s0 = g_b[k];
    int cnt = g_b[k + 1] - s0;          // <= 64 for S <= 32768
    if (cnt <= 0) return;
    if (tid < cnt) sidx[tid] = g_idx[s0 + tid];
    __syncthreads();

    int col = lane * 4;
    // lm per column: hand cols (<42) never NaN -> 0; pad cols 122..127 read
    // g_lipmean[80..85] which are static zeros (never matter: pad values are 0).
    float4 lm;
    lm.x = (col + 0 >= 42) ? g_lipmean[col + 0 - 42] : 0.0f;
    lm.y = (col + 1 >= 42) ? g_lipmean[col + 1 - 42] : 0.0f;
    lm.z = (col + 2 >= 42) ? g_lipmean[col + 2 - 42] : 0.0f;
    lm.w = (col + 3 >= 42) ? g_lipmean[col + 3 - 42] : 0.0f;

    float4 a0 = make_float4(0.f, 0.f, 0.f, 0.f);
    float4 a1 = make_float4(0.f, 0.f, 0.f, 0.f);
    int i = w;
    for (; i + 8 < cnt; i += 16) {
        float4 v0 = *(const float4*)(g_scratch + (size_t)sidx[i]     * SCW + col);
        float4 v1 = *(const float4*)(g_scratch + (size_t)sidx[i + 8] * SCW + col);
        a0.x += (v0.x == v0.x) ? v0.x : lm.x;
        a0.y += (v0.y == v0.y) ? v0.y : lm.y;
        a0.z += (v0.z == v0.z) ? v0.z : lm.z;
        a0.w += (v0.w == v0.w) ? v0.w : lm.w;
        a1.x += (v1.x == v1.x) ? v1.x : lm.x;
        a1.y += (v1.y == v1.y) ? v1.y : lm.y;
        a1.z += (v1.z == v1.z) ? v1.z : lm.z;
        a1.w += (v1.w == v1.w) ? v1.w : lm.w;
    }
    for (; i < cnt; i += 8) {
        float4 v = *(const float4*)(g_scratch + (size_t)sidx[i] * SCW + col);
        a0.x += (v.x == v.x) ? v.x : lm.x;
        a0.y += (v.y == v.y) ? v.y : lm.y;
        a0.z += (v.z == v.z) ? v.z : lm.z;
        a0.w += (v.w == v.w) ? v.w : lm.w;
    }
    a0.x += a1.x; a0.y += a1.y; a0.z += a1.z; a0.w += a1.w;
    *(float4*)&part[w][col] = a0;
    __syncthreads();

    if (tid < NCOL) {
        float s = 0.f;
        #pragma unroll
        for (int q = 0; q < 8; q++) s += part[q][tid];
        out[(size_t)g_rowoff[k] * NCOL + tid] = s / (float)cnt;
    }
}

// ------------------------- launch -------------------------------------------
extern "C" void kernel_launch(void* const* d_in, const int* in_sizes, int n_in,
                              void* d_out, int out_size) {
    const float* frames = (const float*)d_in[0];
    const int*   lips   = (const int*)d_in[1];

    k1<<<NB1, 256>>>(frames, lips);
    k2<<<1, 256>>>();
    k2b<<<256, 128>>>();
    k3<<<NL, 256>>>((float*)d_out);
}